// round 13
// baseline (speedup 1.0000x reference)
#include <cuda_runtime.h>
#include <cuda_bf16.h>

// Shapes (fixed): B=1, C=8, O=8, G=12, X=Y=Z=12, H=8, W=40, Bb=7 (basis), 27 taps
// x      : (1,8,12,12,12,8,40) f32   strides: c 552960, xi 46080, yi 3840, zi 320, h 40, w 1
// weight : (8,8,3,3,3,7)       f32   o 1512, c 189, f 7, b 1
// bias   : (8,3,3,3)           f32
// basis  : (12,7,3,3)          f32   g 63
// out    : (1,96,12,12,12,8,40) f32
//
// Factored algorithm:
//   Y[b,o,h,w]   = sum_{c,f} x[c, n+f, h, w] * weight[o,c,f,b]          (per n)
//   out[g*8+o,.] = biasSum[o] + sum_{b,u,v} basis[(g+border)%12,b,u,v] * Y[b,o,hh0+u,ww0+v]
// SINGLE kernel: one CTA per cell (729), NT=320, 104KB smem, 2 CTAs/SM.
// Scalar FFMA phase 1 (measured pipe wall), FFMA2 phase 2. All constants staged
// in-CTA from raw inputs (no prep kernel). Shell zeroing interleaved in the
// f-loop as fire-and-forget STG.128 with incremental carry indexing.

#define NT 320
// smem floats: sWf[2*512] + sBp[2016] + sBiasS[16] + sX[2*2560] + sY[56*320]
#define SMEM_FLOATS (1024 + 2016 + 16 + 5120 + 17920)
#define SMEM_BYTES (SMEM_FLOATS * 4)

#define TOT_SLOTS (96 * 1728 * 80)    // all float4 slots in out (13,271,040)
#define NTHREADS  (729 * NT)          // stride: +1 go-channel + 1188 cells
                                      // 1188 cells = +8 cx, +3 cy, +0 cz

typedef unsigned long long ull;

__device__ __forceinline__ void fma2(ull& d, ull a, ull b) {
    asm("fma.rn.f32x2 %0, %1, %2, %0;" : "+l"(d) : "l"(a), "l"(b));
}
__device__ __forceinline__ ull pack2(float lo, float hi) {
    ull r; asm("mov.b64 %0, {%1, %2};" : "=l"(r) : "f"(lo), "f"(hi)); return r;
}
__device__ __forceinline__ void unpack2(float& lo, float& hi, ull v) {
    asm("mov.b64 {%0, %1}, %2;" : "=f"(lo), "=f"(hi) : "l"(v));
}

__global__ __launch_bounds__(NT, 2)
void gconv_main(const float* __restrict__ x,
                const float* __restrict__ weight,
                const float* __restrict__ bias,
                const float* __restrict__ basis,
                float* __restrict__ out)
{
    extern __shared__ float smem[];
    float* sWf    = smem;            // [2][8c][64]  double-buffered weight plane
    float* sBp    = sWf + 1024;      // [2][63][16]  pre-rotated basis
    float* sBiasS = sBp + 2016;      // [8] (+8 pad)
    float* sX     = sBiasS + 16;     // [2][8][320]  double-buffered x plane
    float* sY     = sX + 5120;       // [56][320]    (o*7+b) x pix

    const int tid  = threadIdx.x;
    const int cell = blockIdx.x;
    const int xi = cell / 81, yi = (cell / 9) % 9, zi = cell % 9;

    // ---- shell-zero iterator state (address map is linear: addr = slot*16B) ----
    const int slot0 = cell * NT + tid;
    float4* zp = reinterpret_cast<float4*>(out) + slot0;
    int zcx, zcy; bool zcOut; int zkmax;
    {
        int r   = slot0 % 138240;        // within one go-channel
        int cel = r / 80;
        zcx = cel / 144;
        int r2 = cel % 144;
        zcy = r2 / 12;
        int cz = r2 % 12;
        zcOut = (cz < 1) | (cz > 9);     // per-thread constant (cz never changes)
        zkmax = (slot0 < TOT_SLOTS - 56 * NTHREADS) ? 57 : 56;
    }
    const float4 z4 = make_float4(0.f, 0.f, 0.f, 0.f);

#define SHELL_STEP()                                                        \
    {                                                                       \
        if (((unsigned)(zcx - 1) > 8u) | ((unsigned)(zcy - 1) > 8u) | zcOut)\
            *zp = z4;                                                       \
        zp += NTHREADS;                                                     \
        zcy += 3; zcx += 8;                                                 \
        if (zcy >= 12) { zcy -= 12; zcx++; }                                \
        if (zcx >= 12) zcx -= 12;                                           \
    }

    // ---- stage small constants from RAW inputs (no prep kernel) ----
    {
        // sBp[s][kk][g16] = basis[(g+s)%12][kk]; g>=12 pad 0
        for (int i = tid; i < 2016; i += NT) {
            int s  = (i >= 1008) ? 1 : 0;
            int r  = i - s * 1008;
            int kk = r >> 4;
            int g  = r & 15;
            int ge = g + s; if (ge >= 12) ge -= 12;
            sBp[i] = (g < 12) ? basis[ge * 63 + kk] : 0.f;
        }
        if (tid < 8) {
            float s = 0.f;
            #pragma unroll
            for (int t = 0; t < 27; t++) s += bias[tid * 27 + t];
            sBiasS[tid] = s;
        }
    }

    // ---- Phase 1: Y[o*7+b][pix]; thread = (o-pair op, 4 consecutive px) ----
    const int op  = tid / 80;          // 0..3 -> o in {2op, 2op+1}
    const int t_q = tid % 80;          // px 4*t_q .. 4*t_q+3

    float acc[2][7][4];
    #pragma unroll
    for (int t = 0; t < 2; t++)
        #pragma unroll
        for (int i = 0; i < 7; i++)
            #pragma unroll
            for (int j = 0; j < 4; j++) acc[t][i][j] = 0.f;

    const float* xn = x + (size_t)xi * 46080 + (size_t)yi * 3840 + (size_t)zi * 320;

    // staging roles: x plane = 640 float4 (2/thread);
    // weight plane = 512 scalars (2 per thread for tid<256), direct from weight[]
    const int cA0 = tid / 80,         pA0 = tid % 80;
    const int cA1 = (tid + 320) / 80, pA1 = (tid + 320) % 80;

    // weight element roles (idx0 = tid, idx1 = tid+256), layout sWf[c*64+o*8+b]
    int wAddr0 = 0, wAddr1 = 0; bool wOk0 = false, wOk1 = false;
    if (tid < 256) {
        int i0 = tid,        c0 = i0 >> 6, col0 = i0 & 63, o0 = col0 >> 3, b0 = col0 & 7;
        int i1 = tid + 256,  c1 = i1 >> 6, col1 = i1 & 63, o1 = col1 >> 3, b1 = col1 & 7;
        wOk0 = (b0 < 7); wAddr0 = o0 * 1512 + c0 * 189 + b0;
        wOk1 = (b1 < 7); wAddr1 = o1 * 1512 + c1 * 189 + b1;
    }

    float4 preX0, preX1;
    float preW0 = 0.f, preW1 = 0.f;
    {
        const float4* xb4 = reinterpret_cast<const float4*>(xn);
        preX0 = xb4[(size_t)cA0 * 138240 + pA0];
        preX1 = xb4[(size_t)cA1 * 138240 + pA1];
        if (tid < 256) {
            if (wOk0) preW0 = weight[wAddr0];
            if (wOk1) preW1 = weight[wAddr1];
        }
    }

    for (int f = 0; f < 27; f++) {
        const int buf = f & 1;
        reinterpret_cast<float4*>(sX + buf * 2560)[cA0 * 80 + pA0] = preX0;
        reinterpret_cast<float4*>(sX + buf * 2560)[cA1 * 80 + pA1] = preX1;
        if (tid < 256) {
            sWf[buf * 512 + tid]       = preW0;
            sWf[buf * 512 + tid + 256] = preW1;
        }
        if (f < 26) {
            const int fn = f + 1;
            const int fi = fn / 9, fj = (fn / 3) % 3, fk = fn % 3;
            const float4* xb4 = reinterpret_cast<const float4*>(
                xn + fi * 46080 + fj * 3840 + fk * 320);
            preX0 = xb4[(size_t)cA0 * 138240 + pA0];
            preX1 = xb4[(size_t)cA1 * 138240 + pA1];
            if (tid < 256) {
                wAddr0 += 7; wAddr1 += 7;
                if (wOk0) preW0 = weight[wAddr0];
                if (wOk1) preW1 = weight[wAddr1];
            }
        }
        __syncthreads();
        // two fire-and-forget shell zeros per f-step (54 of <=57 total)
        SHELL_STEP();
        SHELL_STEP();
        const float* xs = sX + buf * 2560;
        const float* wf = sWf + buf * 512;
        #pragma unroll
        for (int c = 0; c < 8; c++) {
            float4 xv = *reinterpret_cast<const float4*>(xs + c * 320 + t_q * 4);
            float xr[4] = {xv.x, xv.y, xv.z, xv.w};
            #pragma unroll
            for (int t = 0; t < 2; t++) {
                const float* wp = wf + c * 64 + (op * 2 + t) * 8;
                float4 w0 = *reinterpret_cast<const float4*>(wp);
                float4 w1 = *reinterpret_cast<const float4*>(wp + 4);
                float wr[7] = {w0.x, w0.y, w0.z, w0.w, w1.x, w1.y, w1.z};
                #pragma unroll
                for (int i = 0; i < 7; i++)
                    #pragma unroll
                    for (int j = 0; j < 4; j++)
                        acc[t][i][j] = fmaf(wr[i], xr[j], acc[t][i][j]);
            }
        }
    }
    __syncthreads();
    #pragma unroll
    for (int t = 0; t < 2; t++)
        #pragma unroll
        for (int i = 0; i < 7; i++) {
            float4 v = make_float4(acc[t][i][0], acc[t][i][1], acc[t][i][2], acc[t][i][3]);
            *reinterpret_cast<float4*>(sY + ((op * 2 + t) * 7 + i) * 320 + t_q * 4) = v;
        }
    __syncthreads();

    // ---- Phase 2: thread = pixel; two passes over o-halves, 12 g (6 pairs) x 4 o ----
    const int h = tid / 40, w = tid % 40;
    const int hh0 = min(max(h, 1), 6) - 1;
    const int ww0 = min(max(w, 1), 38) - 1;
    const int bshift = ((h == 0) | (h == 7) | (w == 0) | (w == 39)) ? 1 : 0;
    const float* bas = sBp + bshift * 1008;   // [63][16] pre-rotated

    for (int pass = 0; pass < 2; pass++) {
        ull accP[6][4];
        #pragma unroll
        for (int o = 0; o < 4; o++) {
            float bs = sBiasS[pass * 4 + o];
            ull bp = pack2(bs, bs);
            #pragma unroll
            for (int k = 0; k < 6; k++) accP[k][o] = bp;
        }

        const int ybase = pass * 4 * 7 * 320;
        for (int b = 0; b < 7; b++) {
            #pragma unroll
            for (int u = 0; u < 3; u++) {
                #pragma unroll
                for (int v = 0; v < 3; v++) {
                    const int kk = b * 9 + u * 3 + v;
                    const int yoff = (hh0 + u) * 40 + (ww0 + v);
                    ull yd[4];
                    #pragma unroll
                    for (int o = 0; o < 4; o++) {
                        float yv = sY[ybase + (o * 7 + b) * 320 + yoff];
                        yd[o] = pack2(yv, yv);
                    }
                    const ulonglong2* bp = reinterpret_cast<const ulonglong2*>(bas + kk * 16);
                    ulonglong2 b01 = bp[0];   // g-pairs (0,1),(2,3)
                    ulonglong2 b23 = bp[1];   // (4,5),(6,7)
                    ulonglong2 b45 = bp[2];   // (8,9),(10,11)
                    #pragma unroll
                    for (int o = 0; o < 4; o++) {
                        fma2(accP[0][o], b01.x, yd[o]);
                        fma2(accP[1][o], b01.y, yd[o]);
                        fma2(accP[2][o], b23.x, yd[o]);
                        fma2(accP[3][o], b23.y, yd[o]);
                        fma2(accP[4][o], b45.x, yd[o]);
                        fma2(accP[5][o], b45.y, yd[o]);
                    }
                }
            }
        }

        // ---- store: out[(2k+e)*8 + pass*4 + o, xi+1, yi+1, zi+1, px] ----
        float* ob = out + (size_t)(xi + 1) * 46080 + (size_t)(yi + 1) * 3840
                        + (size_t)(zi + 1) * 320 + tid + (size_t)pass * 4 * 552960;
        #pragma unroll
        for (int k = 0; k < 6; k++)
            #pragma unroll
            for (int o = 0; o < 4; o++) {
                float lo, hi;
                unpack2(lo, hi, accP[k][o]);
                ob[(size_t)((2 * k) * 8 + o) * 552960]     = lo;
                ob[(size_t)((2 * k + 1) * 8 + o) * 552960] = hi;
            }
    }

    // ---- drain remaining shell zeros (steps 54 .. zkmax-1, at most 3) ----
    for (int k = 54; k < zkmax; k++)
        SHELL_STEP();
#undef SHELL_STEP
}

extern "C" void kernel_launch(void* const* d_in, const int* in_sizes, int n_in,
                              void* d_out, int out_size)
{
    const float* x      = (const float*)d_in[0];
    const float* weight = (const float*)d_in[1];
    const float* bias   = (const float*)d_in[2];
    const float* basis  = (const float*)d_in[3];
    // d_in[4..7] = I, J, T, bias_basis: deterministic clip/border maps, computed inline.
    float* out = (float*)d_out;

    cudaFuncSetAttribute(gconv_main, cudaFuncAttributeMaxDynamicSharedMemorySize, SMEM_BYTES);

    gconv_main<<<729, NT, SMEM_BYTES>>>(x, weight, bias, basis, out);
}

// round 14
// speedup vs baseline: 1.2891x; 1.2891x over previous
#include <cuda_runtime.h>
#include <cuda_bf16.h>

// Shapes (fixed): B=1, C=8, O=8, G=12, X=Y=Z=12, H=8, W=40, Bb=7 (basis), 27 taps
// x      : (1,8,12,12,12,8,40) f32   strides: c 552960, xi 46080, yi 3840, zi 320, h 40, w 1
// weight : (8,8,3,3,3,7)       f32
// bias   : (8,3,3,3)           f32
// basis  : (12,7,3,3)          f32
// out    : (1,96,12,12,12,8,40) f32
//
// Factored algorithm:
//   Y[b,o,h,w]   = sum_{c,f} x[c, n+f, h, w] * weight[o,c,f,b]          (per n)
//   out[g*8+o,.] = biasSum[o] + sum_{b,u,v} basis[(g+border)%12,b,u,v] * Y[b,o,hh0+u,ww0+v]
// One CTA per cell (729), NT=320, 104KB smem, 2 CTAs/SM. Scalar FFMA phase 1
// (measured pipe wall), FFMA2 phase 2. Shell zeroing interleaved in the f-loop.
// prep_kernel reorganizes constants; gconv launched with PDL so its prologue
// (shell init + x prefetch) overlaps prep; gW/gBp reads gated by
// cudaGridDependencySynchronize().

#define NT 320
// smem floats: sWf[2*512] + sBp[2016] + sBiasS[16] + sX[2*2560] + sY[56*320]
#define SMEM_FLOATS (1024 + 2016 + 16 + 5120 + 17920)
#define SMEM_BYTES (SMEM_FLOATS * 4)

#define TOT_SLOTS (96 * 1728 * 80)    // all float4 slots in out (13,271,040)
#define NTHREADS  (729 * NT)          // stride: +1 go-channel + 1188 cells
                                      // 1188 cells = +8 cx, +3 cy, +0 cz

typedef unsigned long long ull;

__device__ __forceinline__ void fma2(ull& d, ull a, ull b) {
    asm("fma.rn.f32x2 %0, %1, %2, %0;" : "+l"(d) : "l"(a), "l"(b));
}
__device__ __forceinline__ ull pack2(float lo, float hi) {
    ull r; asm("mov.b64 %0, {%1, %2};" : "=l"(r) : "f"(lo), "f"(hi)); return r;
}
__device__ __forceinline__ void unpack2(float& lo, float& hi, ull v) {
    asm("mov.b64 {%0, %1}, %2;" : "=f"(lo), "=f"(hi) : "l"(v));
}

__device__ float gW[27 * 512];      // [f][c][o*8+b], b==7 zero-padded
__device__ float gBp[2 * 63 * 16];  // [shift][kk][g(12, pad 16)]: pre-rotated basis
__device__ float gBiasS[8];

// One-shot prep: gW/gBp/gBiasS reorganization. 28 blocks x 512.
__global__ __launch_bounds__(512)
void prep_kernel(const float* __restrict__ weight,
                 const float* __restrict__ bias,
                 const float* __restrict__ basis)
{
    const int blk = blockIdx.x, tid = threadIdx.x;

    if (blk < 27) {               // 27*512 = 13824 = gW elements
        int idx = blk * 512 + tid;
        int f   = idx >> 9;
        int rem = idx & 511;
        int c   = rem >> 6;
        int col = rem & 63;
        int o = col >> 3, b = col & 7;
        gW[idx] = (b < 7) ? weight[o * 1512 + c * 189 + f * 7 + b] : 0.f;
    } else {
        if (tid < 8) {
            float s = 0.f;
            #pragma unroll
            for (int t = 0; t < 27; t++) s += bias[tid * 27 + t];
            gBiasS[tid] = s;
        }
        for (int i = tid; i < 2016; i += 512) {
            int s  = i / 1008;
            int kk = (i % 1008) >> 4;
            int g  = i & 15;
            int ge = g + s; if (ge >= 12) ge -= 12;
            gBp[i] = (g < 12) ? basis[ge * 63 + kk] : 0.f;
        }
    }
}

__global__ __launch_bounds__(NT, 2)
void gconv_main(const float* __restrict__ x, float* __restrict__ out)
{
    extern __shared__ float smem[];
    float* sWf    = smem;            // [2][8c][64]  double-buffered weight plane
    float* sBp    = sWf + 1024;      // [2][63][16]
    float* sBiasS = sBp + 2016;      // [8] (+8 pad)
    float* sX     = sBiasS + 16;     // [2][8][320]  double-buffered x plane
    float* sY     = sX + 5120;       // [56][320]    (o*7+b) x pix

    const int tid  = threadIdx.x;
    const int cell = blockIdx.x;
    const int xi = cell / 81, yi = (cell / 9) % 9, zi = cell % 9;

    // ==== PDL-independent prologue (overlaps prep_kernel) ====

    // ---- shell-zero iterator state (address map is linear: addr = slot*16B) ----
    const int slot0 = cell * NT + tid;
    float4* zp = reinterpret_cast<float4*>(out) + slot0;
    int zcx, zcy; bool zcOut; int zkmax;
    {
        int r   = slot0 % 138240;        // within one go-channel
        int cel = r / 80;
        zcx = cel / 144;
        int r2 = cel % 144;
        zcy = r2 / 12;
        int cz = r2 % 12;
        zcOut = (cz < 1) | (cz > 9);     // per-thread constant (cz never changes)
        zkmax = (slot0 < TOT_SLOTS - 56 * NTHREADS) ? 57 : 56;
    }
    const float4 z4 = make_float4(0.f, 0.f, 0.f, 0.f);

#define SHELL_STEP()                                                        \
    {                                                                       \
        if (((unsigned)(zcx - 1) > 8u) | ((unsigned)(zcy - 1) > 8u) | zcOut)\
            *zp = z4;                                                       \
        zp += NTHREADS;                                                     \
        zcy += 3; zcx += 8;                                                 \
        if (zcy >= 12) { zcy -= 12; zcx++; }                                \
        if (zcx >= 12) zcx -= 12;                                           \
    }

    // ---- x-plane prefetch (depends only on x) ----
    const int op  = tid / 80;          // 0..3 -> o in {2op, 2op+1}
    const int t_q = tid % 80;          // px 4*t_q .. 4*t_q+3
    const int cA0 = tid / 80,         pA0 = tid % 80;
    const int cA1 = (tid + 320) / 80, pA1 = (tid + 320) % 80;

    const float* xn = x + (size_t)xi * 46080 + (size_t)yi * 3840 + (size_t)zi * 320;

    float4 preX0, preX1, preW;
    {
        const float4* xb4 = reinterpret_cast<const float4*>(xn);
        preX0 = xb4[(size_t)cA0 * 138240 + pA0];
        preX1 = xb4[(size_t)cA1 * 138240 + pA1];
    }

    // ==== wait for prep_kernel's gW/gBp/gBiasS ====
    cudaGridDependencySynchronize();

    // ---- stage small constants ----
    {
        float4* b4 = reinterpret_cast<float4*>(sBp);
        const float4* gb4 = reinterpret_cast<const float4*>(gBp);
        for (int i = tid; i < 504; i += NT) b4[i] = gb4[i];
        if (tid < 8) sBiasS[tid] = gBiasS[tid];
    }

    const float4* gW4 = reinterpret_cast<const float4*>(gW);
    if (tid < 128) preW = gW4[tid];

    // ---- Phase 1: Y[o*7+b][pix]; thread = (o-pair op, 4 consecutive px) ----
    float acc[2][7][4];
    #pragma unroll
    for (int t = 0; t < 2; t++)
        #pragma unroll
        for (int i = 0; i < 7; i++)
            #pragma unroll
            for (int j = 0; j < 4; j++) acc[t][i][j] = 0.f;

    for (int f = 0; f < 27; f++) {
        const int buf = f & 1;
        reinterpret_cast<float4*>(sX + buf * 2560)[cA0 * 80 + pA0] = preX0;
        reinterpret_cast<float4*>(sX + buf * 2560)[cA1 * 80 + pA1] = preX1;
        if (tid < 128)
            reinterpret_cast<float4*>(sWf + buf * 512)[tid] = preW;
        if (f < 26) {
            const int fn = f + 1;
            const int fi = fn / 9, fj = (fn / 3) % 3, fk = fn % 3;
            const float4* xb4 = reinterpret_cast<const float4*>(
                xn + fi * 46080 + fj * 3840 + fk * 320);
            preX0 = xb4[(size_t)cA0 * 138240 + pA0];
            preX1 = xb4[(size_t)cA1 * 138240 + pA1];
            if (tid < 128) preW = gW4[fn * 128 + tid];
        }
        __syncthreads();
        // two fire-and-forget shell zeros per f-step (54 of <=57 total)
        SHELL_STEP();
        SHELL_STEP();
        const float* xs = sX + buf * 2560;
        const float* wf = sWf + buf * 512;
        #pragma unroll
        for (int c = 0; c < 8; c++) {
            float4 xv = *reinterpret_cast<const float4*>(xs + c * 320 + t_q * 4);
            float xr[4] = {xv.x, xv.y, xv.z, xv.w};
            #pragma unroll
            for (int t = 0; t < 2; t++) {
                const float* wp = wf + c * 64 + (op * 2 + t) * 8;
                float4 w0 = *reinterpret_cast<const float4*>(wp);
                float4 w1 = *reinterpret_cast<const float4*>(wp + 4);
                float wr[7] = {w0.x, w0.y, w0.z, w0.w, w1.x, w1.y, w1.z};
                #pragma unroll
                for (int i = 0; i < 7; i++)
                    #pragma unroll
                    for (int j = 0; j < 4; j++)
                        acc[t][i][j] = fmaf(wr[i], xr[j], acc[t][i][j]);
            }
        }
    }
    __syncthreads();
    #pragma unroll
    for (int t = 0; t < 2; t++)
        #pragma unroll
        for (int i = 0; i < 7; i++) {
            float4 v = make_float4(acc[t][i][0], acc[t][i][1], acc[t][i][2], acc[t][i][3]);
            *reinterpret_cast<float4*>(sY + ((op * 2 + t) * 7 + i) * 320 + t_q * 4) = v;
        }
    __syncthreads();

    // ---- Phase 2: thread = pixel; two passes over o-halves, 12 g (6 pairs) x 4 o ----
    const int h = tid / 40, w = tid % 40;
    const int hh0 = min(max(h, 1), 6) - 1;
    const int ww0 = min(max(w, 1), 38) - 1;
    const int bshift = ((h == 0) | (h == 7) | (w == 0) | (w == 39)) ? 1 : 0;
    const float* bas = sBp + bshift * 1008;   // [63][16] pre-rotated

    for (int pass = 0; pass < 2; pass++) {
        ull accP[6][4];
        #pragma unroll
        for (int o = 0; o < 4; o++) {
            float bs = sBiasS[pass * 4 + o];
            ull bp = pack2(bs, bs);
            #pragma unroll
            for (int k = 0; k < 6; k++) accP[k][o] = bp;
        }

        const int ybase = pass * 4 * 7 * 320;
        for (int b = 0; b < 7; b++) {
            #pragma unroll
            for (int u = 0; u < 3; u++) {
                #pragma unroll
                for (int v = 0; v < 3; v++) {
                    const int kk = b * 9 + u * 3 + v;
                    const int yoff = (hh0 + u) * 40 + (ww0 + v);
                    ull yd[4];
                    #pragma unroll
                    for (int o = 0; o < 4; o++) {
                        float yv = sY[ybase + (o * 7 + b) * 320 + yoff];
                        yd[o] = pack2(yv, yv);
                    }
                    const ulonglong2* bp = reinterpret_cast<const ulonglong2*>(bas + kk * 16);
                    ulonglong2 b01 = bp[0];   // g-pairs (0,1),(2,3)
                    ulonglong2 b23 = bp[1];   // (4,5),(6,7)
                    ulonglong2 b45 = bp[2];   // (8,9),(10,11)
                    #pragma unroll
                    for (int o = 0; o < 4; o++) {
                        fma2(accP[0][o], b01.x, yd[o]);
                        fma2(accP[1][o], b01.y, yd[o]);
                        fma2(accP[2][o], b23.x, yd[o]);
                        fma2(accP[3][o], b23.y, yd[o]);
                        fma2(accP[4][o], b45.x, yd[o]);
                        fma2(accP[5][o], b45.y, yd[o]);
                    }
                }
            }
        }

        // ---- store: out[(2k+e)*8 + pass*4 + o, xi+1, yi+1, zi+1, px] ----
        float* ob = out + (size_t)(xi + 1) * 46080 + (size_t)(yi + 1) * 3840
                        + (size_t)(zi + 1) * 320 + tid + (size_t)pass * 4 * 552960;
        #pragma unroll
        for (int k = 0; k < 6; k++)
            #pragma unroll
            for (int o = 0; o < 4; o++) {
                float lo, hi;
                unpack2(lo, hi, accP[k][o]);
                ob[(size_t)((2 * k) * 8 + o) * 552960]     = lo;
                ob[(size_t)((2 * k + 1) * 8 + o) * 552960] = hi;
            }
    }

    // ---- drain remaining shell zeros (steps 54 .. zkmax-1, at most 3) ----
    for (int k = 54; k < zkmax; k++)
        SHELL_STEP();
#undef SHELL_STEP
}

extern "C" void kernel_launch(void* const* d_in, const int* in_sizes, int n_in,
                              void* d_out, int out_size)
{
    const float* x      = (const float*)d_in[0];
    const float* weight = (const float*)d_in[1];
    const float* bias   = (const float*)d_in[2];
    const float* basis  = (const float*)d_in[3];
    // d_in[4..7] = I, J, T, bias_basis: deterministic clip/border maps, computed inline.
    float* out = (float*)d_out;

    cudaFuncSetAttribute(gconv_main, cudaFuncAttributeMaxDynamicSharedMemorySize, SMEM_BYTES);

    prep_kernel<<<28, 512>>>(weight, bias, basis);

    // PDL launch: gconv CTAs start while prep finishes; device-side
    // cudaGridDependencySynchronize() gates the gW/gBp reads.
    cudaLaunchConfig_t cfg = {};
    cfg.gridDim  = dim3(729, 1, 1);
    cfg.blockDim = dim3(NT, 1, 1);
    cfg.dynamicSmemBytes = SMEM_BYTES;
    cfg.stream = 0;
    cudaLaunchAttribute attr[1];
    attr[0].id = cudaLaunchAttributeProgrammaticStreamSerialization;
    attr[0].val.programmaticStreamSerializationAllowed = 1;
    cfg.attrs = attr;
    cfg.numAttrs = 1;
    cudaError_t e = cudaLaunchKernelEx(&cfg, gconv_main, x, out);
    if (e != cudaSuccess) {
        // Fallback: plain stream-ordered launch (device-side wait is a no-op
        // once the dependency is already satisfied by stream order).
        gconv_main<<<729, NT, SMEM_BYTES>>>(x, out);
    }
}